// round 4
// baseline (speedup 1.0000x reference)
#include <cuda_runtime.h>

#define NN 524288
#define EE 8388608
#define NPG 8192
#define NB 64
#define NWORDS (NN/32)
#define CAP0 (1<<16)
#define CAP1 (1<<20)
#define CAP2 (1<<22)

__device__ __align__(128) float g_deg[NN];
__device__ __align__(128) float g_hs[NN*8];    // dis[s]*h1[s]
__device__ __align__(128) float g_acc1[NN*8];
__device__ __align__(128) float g_h2s[NN*8];   // dis*h2
__device__ __align__(128) float g_acc2[NN*8];
__device__ __align__(128) float g_h3s[NN];
__device__ __align__(128) float g_acc3[NN];
__device__ unsigned g_bm0[NWORDS];   // targets
__device__ unsigned g_bmG[NWORDS];   // growing frontier: S1 -> S2 -> S3
__device__ int g_list0[CAP0];        // edges into targets
__device__ int g_list1[CAP1];        // edges into S1
__device__ int g_list2[CAP2];        // edges into S2
__device__ int g_nl1[NN], g_nl2[NN], g_nl3[NN];
__device__ int g_cnt0, g_cnt1, g_cnt2, g_cntn1, g_cntn2, g_cntn3;

__device__ __forceinline__ bool bmtest(const unsigned* bm, int i){ return (bm[i>>5]>>(i&31))&1u; }
__device__ __forceinline__ void bmset(unsigned* bm, int i){ atomicOr(&bm[i>>5], 1u<<(i&31)); }

// warp-aggregated append; callers must be full warps with uniform control flow
__device__ __forceinline__ void wappend(bool pred, int val, int* cnt, int* list, int cap){
  unsigned m = __ballot_sync(0xffffffffu, pred);
  if (!m) return;
  int lane = threadIdx.x & 31;
  int leader = __ffs(m) - 1;
  int base = 0;
  if (lane == leader) base = atomicAdd(cnt, __popc(m));
  base = __shfl_sync(0xffffffffu, base, leader);
  if (pred){
    int p = base + __popc(m & ((1u<<lane)-1u));
    if (p < cap) list[p] = val;
  }
}

__global__ void k_init(){
  int i = blockIdx.x*blockDim.x + threadIdx.x;
  g_deg[i] = 1.0f;                         // self-loop
  if (i < NWORDS){ g_bm0[i]=0u; g_bmG[i]=0u; }
  if (i == 0){ g_cnt0=0; g_cnt1=0; g_cnt2=0; g_cntn1=0; g_cntn2=0; g_cntn3=0; }
}

__global__ void k_mark(const int* __restrict__ tgt){
  int g = threadIdx.x;
  int t = g*NPG + tgt[g];
  bmset(g_bm0, t); bmset(g_bmG, t);
}

// scan dst, collect edges whose dst is in the chosen bitmap
__global__ __launch_bounds__(256) void k_scan(const int* __restrict__ dstp, int which){
  int e = blockIdx.x*blockDim.x + threadIdx.x;
  int d = dstp[e];
  if (which == 0)      wappend(bmtest(g_bm0, d), e, &g_cnt0, g_list0, CAP0);
  else if (which == 1) wappend(bmtest(g_bmG, d), e, &g_cnt1, g_list1, CAP1);
  else                 wappend(bmtest(g_bmG, d), e, &g_cnt2, g_list2, CAP2);
}

// mark srcs of a list into bmG (frontier growth)
__global__ void k_srcs(const int* __restrict__ srcp, int which){
  const int* list = (which==0) ? g_list0 : (which==1) ? g_list1 : g_list2;
  int cap         = (which==0) ? CAP0    : (which==1) ? CAP1    : CAP2;
  int n   = min((which==0) ? g_cnt0 : (which==1) ? g_cnt1 : g_cnt2, cap);
  int stride = gridDim.x*blockDim.x;
  for (int i = blockIdx.x*blockDim.x + threadIdx.x; i < n; i += stride)
    bmset(g_bmG, srcp[list[i]]);
}

// snapshot current bmG into node list `which` (1,2,3)
__global__ void k_compact(int which){
  int i = blockIdx.x*blockDim.x + threadIdx.x;
  bool p = bmtest(g_bmG, i);
  if (which == 1)      wappend(p, i, &g_cntn1, g_nl1, NN);
  else if (which == 2) wappend(p, i, &g_cntn2, g_nl2, NN);
  else                 wappend(p, i, &g_cntn3, g_nl3, NN);
}

// degree, only where needed (dst in S3)
__global__ __launch_bounds__(256) void k_degS(const int* __restrict__ dstp){
  int e = blockIdx.x*blockDim.x + threadIdx.x;
  int d = dstp[e];
  if (bmtest(g_bmG, d)) atomicAdd(&g_deg[d], 1.0f);
}

// sparse h1: for nodes in nl3, hs = dis*(x@W1); zero acc1. 8 threads/node.
__global__ __launch_bounds__(256) void k_h1s(const float* __restrict__ x,
                                             const float* __restrict__ W1){
  __shared__ float sW[128*9];
  int t = threadIdx.x;
  for (int i = t; i < 1024; i += 256) sW[(i>>3)*9 + (i&7)] = W1[i];
  __syncthreads();
  int gt = blockIdx.x*256 + t;
  int sub = gt & 7;
  int slot = gt >> 3;
  int nslots = (gridDim.x*256) >> 3;
  int n = g_cntn3;
  for (int i = slot; i < n; i += nslots){
    int node = g_nl3[i];
    const float* xr = x + (size_t)node*128 + sub*4;
    float acc[8];
    #pragma unroll
    for (int j=0;j<8;j++) acc[j] = 0.f;
    #pragma unroll
    for (int q=0;q<4;q++){
      float4 v = *(const float4*)(xr + 32*q);
      float xt[4] = {v.x, v.y, v.z, v.w};
      #pragma unroll
      for (int u=0;u<4;u++){
        const float* w = &sW[(32*q + 4*sub + u)*9];
        #pragma unroll
        for (int j=0;j<8;j++) acc[j] += xt[u]*w[j];
      }
    }
    #pragma unroll
    for (int off=4; off; off>>=1){
      #pragma unroll
      for (int j=0;j<8;j++) acc[j] += __shfl_xor_sync(0xffffffffu, acc[j], off);
    }
    if (sub == 0){
      float r = rsqrtf(g_deg[node]);
      float* hp = g_hs + (size_t)node*8;
      *(float4*)hp     = make_float4(acc[0]*r,acc[1]*r,acc[2]*r,acc[3]*r);
      *(float4*)(hp+4) = make_float4(acc[4]*r,acc[5]*r,acc[6]*r,acc[7]*r);
      float* ap = g_acc1 + (size_t)node*8;
      *(float4*)ap     = make_float4(0.f,0.f,0.f,0.f);
      *(float4*)(ap+4) = make_float4(0.f,0.f,0.f,0.f);
    }
  }
}

__global__ __launch_bounds__(256) void k_agg1s(const int* __restrict__ srcp, const int* __restrict__ dstp){
  int n = min(g_cnt2, CAP2);
  int stride = gridDim.x*blockDim.x;
  for (int i = blockIdx.x*blockDim.x + threadIdx.x; i < n; i += stride){
    int e = g_list2[i];
    int s = srcp[e], d = dstp[e];
    const float* hp = g_hs + (size_t)s*8;
    float4 a = *(const float4*)hp, b = *(const float4*)(hp+4);
    float* ap = g_acc1 + (size_t)d*8;
    atomicAdd((float4*)ap, a);
    atomicAdd((float4*)(ap+4), b);
  }
}

// x1 = relu(dis*(acc1+hs)+b1); h2s = dis*(x1@W2); zero acc2. nodes in nl2.
__global__ __launch_bounds__(256) void k_h2(const float* __restrict__ W2, const float* __restrict__ b1){
  __shared__ float sW[64], sb[8];
  int t = threadIdx.x;
  if (t < 64) sW[t] = W2[t];
  if (t < 8)  sb[t] = b1[t];
  __syncthreads();
  int n = g_cntn2;
  int stride = gridDim.x*blockDim.x;
  for (int i = blockIdx.x*blockDim.x + t; i < n; i += stride){
    int node = g_nl2[i];
    float r = rsqrtf(g_deg[node]);
    const float* ap = g_acc1 + (size_t)node*8;
    const float* hp = g_hs  + (size_t)node*8;
    float x1[8];
    #pragma unroll
    for (int j=0;j<8;j++) x1[j] = fmaxf(r*(ap[j]+hp[j]) + sb[j], 0.f);
    float* h2p = g_h2s + (size_t)node*8;
    float* a2  = g_acc2 + (size_t)node*8;
    #pragma unroll
    for (int j=0;j<8;j++){
      float s2 = 0.f;
      #pragma unroll
      for (int u=0;u<8;u++) s2 += x1[u]*sW[u*8+j];
      h2p[j] = r*s2;
      a2[j] = 0.f;
    }
  }
}

__global__ void k_agg2s(const int* __restrict__ srcp, const int* __restrict__ dstp){
  int n = min(g_cnt1, CAP1);
  int stride = gridDim.x*blockDim.x;
  for (int i = blockIdx.x*blockDim.x + threadIdx.x; i < n; i += stride){
    int e = g_list1[i];
    int s = srcp[e], d = dstp[e];
    const float* hp = g_h2s + (size_t)s*8;
    float4 a = *(const float4*)hp, b = *(const float4*)(hp+4);
    float* ap = g_acc2 + (size_t)d*8;
    atomicAdd((float4*)ap, a);
    atomicAdd((float4*)(ap+4), b);
  }
}

// x2 = relu(dis*(acc2+h2s)+b2); h3s = dis*(x2.W3); zero acc3. nodes in nl1.
__global__ void k_h3(const float* __restrict__ W3, const float* __restrict__ b2){
  int n = g_cntn1;
  int stride = gridDim.x*blockDim.x;
  for (int i = blockIdx.x*blockDim.x + threadIdx.x; i < n; i += stride){
    int node = g_nl1[i];
    float r = rsqrtf(g_deg[node]);
    const float* ap = g_acc2 + (size_t)node*8;
    const float* hp = g_h2s + (size_t)node*8;
    float s2 = 0.f;
    #pragma unroll
    for (int j=0;j<8;j++) s2 += fmaxf(r*(ap[j]+hp[j]) + b2[j], 0.f)*W3[j];
    g_h3s[node] = r*s2;
    g_acc3[node] = 0.f;
  }
}

__global__ void k_agg3s(const int* __restrict__ srcp, const int* __restrict__ dstp){
  int n = min(g_cnt0, CAP0);
  int stride = gridDim.x*blockDim.x;
  for (int i = blockIdx.x*blockDim.x + threadIdx.x; i < n; i += stride){
    int e = g_list0[i];
    atomicAdd(&g_acc3[dstp[e]], g_h3s[srcp[e]]);
  }
}

// head: recompute x1,x2,x3 at targets, then 2-layer MLP
__global__ void k_head(const int* __restrict__ tgt,
                       const float* __restrict__ b1, const float* __restrict__ b2,
                       const float* __restrict__ b3,
                       const float* __restrict__ Wl1, const float* __restrict__ bl1,
                       const float* __restrict__ Wl2, const float* __restrict__ bl2,
                       float* __restrict__ out){
  __shared__ float sW1[17*16], sb1[16], sW2[32], sb2[2];
  int t = threadIdx.x;
  for (int i = t; i < 17*16; i += 64) sW1[i] = Wl1[i];
  if (t < 16) sb1[t] = bl1[t];
  if (t < 32) sW2[t] = Wl2[t];
  if (t < 2)  sb2[t] = bl2[t];
  __syncthreads();
  if (t >= NB) return;
  int node = t*NPG + tgt[t];
  float r = rsqrtf(g_deg[node]);
  float f[17];
  const float* a1 = g_acc1 + (size_t)node*8;
  const float* h1 = g_hs  + (size_t)node*8;
  const float* a2 = g_acc2 + (size_t)node*8;
  const float* h2 = g_h2s + (size_t)node*8;
  #pragma unroll
  for (int j=0;j<8;j++) f[j]   = fmaxf(r*(a1[j]+h1[j]) + b1[j], 0.f);
  #pragma unroll
  for (int j=0;j<8;j++) f[8+j] = fmaxf(r*(a2[j]+h2[j]) + b2[j], 0.f);
  f[16] = fmaxf(r*(g_acc3[node]+g_h3s[node]) + b3[0], 0.f);
  float z[16];
  #pragma unroll
  for (int j=0;j<16;j++){
    float s2 = sb1[j];
    #pragma unroll
    for (int u=0;u<17;u++) s2 += f[u]*sW1[u*16+j];
    z[j] = fmaxf(s2, 0.f);
  }
  #pragma unroll
  for (int o=0;o<2;o++){
    float s2 = sb2[o];
    #pragma unroll
    for (int u=0;u<16;u++) s2 += z[u]*sW2[u*2+o];
    out[t*2+o] = s2;
  }
}

extern "C" void kernel_launch(void* const* d_in, const int* in_sizes, int n_in,
                              void* d_out, int out_size){
  const float* x    = (const float*)d_in[0];
  const int*   ei   = (const int*)  d_in[1];
  const int*   tgt  = (const int*)  d_in[2];
  const float* W1   = (const float*)d_in[3];
  const float* b1   = (const float*)d_in[4];
  const float* W2   = (const float*)d_in[5];
  const float* b2   = (const float*)d_in[6];
  const float* W3   = (const float*)d_in[7];
  const float* b3   = (const float*)d_in[8];
  const float* Wl1  = (const float*)d_in[9];
  const float* bl1  = (const float*)d_in[10];
  const float* Wl2  = (const float*)d_in[11];
  const float* bl2  = (const float*)d_in[12];
  const int* srcp = ei;
  const int* dstp = ei + EE;
  float* out = (float*)d_out;

  k_init<<<NN/256, 256>>>();
  k_mark<<<1, 64>>>(tgt);
  k_scan<<<EE/256, 256>>>(dstp, 0);      // list0: edges into targets
  k_srcs<<<64, 256>>>(srcp, 0);          // bmG = S1
  k_compact<<<NN/256, 256>>>(1);         // nl1 = S1
  k_scan<<<EE/256, 256>>>(dstp, 1);      // list1: edges into S1
  k_srcs<<<64, 256>>>(srcp, 1);          // bmG = S2
  k_compact<<<NN/256, 256>>>(2);         // nl2 = S2
  k_scan<<<EE/256, 256>>>(dstp, 2);      // list2: edges into S2
  k_srcs<<<128, 256>>>(srcp, 2);         // bmG = S3
  k_compact<<<NN/256, 256>>>(3);         // nl3 = S3
  k_degS<<<EE/256, 256>>>(dstp);         // deg at S3 nodes only
  k_h1s<<<2048, 256>>>(x, W1);
  k_agg1s<<<512, 256>>>(srcp, dstp);
  k_h2<<<128, 256>>>(W2, b1);
  k_agg2s<<<64, 256>>>(srcp, dstp);
  k_h3<<<64, 256>>>(W3, b2);
  k_agg3s<<<16, 256>>>(srcp, dstp);
  k_head<<<1, 64>>>(tgt, b1, b2, b3, Wl1, bl1, Wl2, bl2, out);
}

// round 5
// speedup vs baseline: 1.2936x; 1.2936x over previous
#include <cuda_runtime.h>

#define NN 524288
#define EE 8388608
#define NPG 8192
#define NB 64
#define NWORDS (NN/32)
#define CAP0 (1<<16)
#define CAP1 (1<<20)
#define CAP2 (1<<22)
#define SCAN_BLOCKS 296
#define SCAN_THREADS 1024

__device__ __align__(128) float g_deg[NN];
__device__ __align__(128) float g_hs[NN*8];    // dis*h1  (prescaled)
__device__ __align__(128) float g_acc1[NN*8];
__device__ __align__(128) float g_h2s[NN*8];   // dis*h2
__device__ __align__(128) float g_acc2[NN*8];
__device__ __align__(128) float g_h3s[NN];
__device__ __align__(128) float g_acc3[NN];
__device__ unsigned g_bm0[NWORDS];   // targets
__device__ unsigned g_bmG[NWORDS];   // growing frontier S1 -> S2
__device__ int g_list0[CAP0];        // edges into targets
__device__ int g_list1[CAP1];        // edges into S1
__device__ int g_list2[CAP2];        // edges into S2
__device__ int g_nl1[NN], g_nl2[NN];
__device__ int g_cnt0, g_cnt1, g_cnt2, g_cntn1, g_cntn2;

__device__ __forceinline__ bool bmtest(const unsigned* bm, int i){ return (bm[i>>5]>>(i&31))&1u; }
__device__ __forceinline__ void bmset(unsigned* bm, int i){ atomicOr(&bm[i>>5], 1u<<(i&31)); }

// warp-aggregated append; every lane of the warp must call this
__device__ __forceinline__ void wappend(bool pred, int val, int* cnt, int* list, int cap){
  unsigned m = __ballot_sync(0xffffffffu, pred);
  if (!m) return;
  int lane = threadIdx.x & 31;
  int leader = __ffs(m) - 1;
  int base = 0;
  if (lane == leader) base = atomicAdd(cnt, __popc(m));
  base = __shfl_sync(0xffffffffu, base, leader);
  if (pred){
    int p = base + __popc(m & ((1u<<lane)-1u));
    if (p < cap) list[p] = val;
  }
}

__global__ void k_init(){
  int i = blockIdx.x*blockDim.x + threadIdx.x;
  g_deg[i] = 1.0f;                         // self-loop
  g_acc3[i] = 0.0f;
  float4 z = make_float4(0.f,0.f,0.f,0.f);
  float4* a1 = (float4*)(g_acc1 + (size_t)i*8);
  float4* a2 = (float4*)(g_acc2 + (size_t)i*8);
  a1[0]=z; a1[1]=z; a2[0]=z; a2[1]=z;
  if (i < NWORDS){ g_bm0[i]=0u; g_bmG[i]=0u; }
  if (i == 0){ g_cnt0=0; g_cnt1=0; g_cnt2=0; g_cntn1=0; g_cntn2=0; }
}

__global__ void k_mark(const int* __restrict__ tgt){
  int g = threadIdx.x;
  int t = g*NPG + tgt[g];
  bmset(g_bm0, t); bmset(g_bmG, t);
}

// dense degree (unconditional atomics) + collect edges into targets via smem bm0
__global__ __launch_bounds__(SCAN_THREADS) void k_degscan0(const int* __restrict__ dstp){
  extern __shared__ unsigned sbm[];
  for (int i = threadIdx.x; i < NWORDS; i += SCAN_THREADS) sbm[i] = g_bm0[i];
  __syncthreads();
  const int EV = EE/4;
  int stride = gridDim.x*blockDim.x;
  int gtid = blockIdx.x*blockDim.x + threadIdx.x;
  int iters = (EV + stride - 1)/stride;
  for (int it = 0; it < iters; it++){
    int i = gtid + it*stride;
    bool v = i < EV;
    int4 d4 = make_int4(0,0,0,0);
    if (v){
      d4 = ((const int4*)dstp)[i];
      atomicAdd(&g_deg[d4.x],1.f); atomicAdd(&g_deg[d4.y],1.f);
      atomicAdd(&g_deg[d4.z],1.f); atomicAdd(&g_deg[d4.w],1.f);
    }
    int e0 = 4*i;
    wappend(v && ((sbm[d4.x>>5]>>(d4.x&31))&1u), e0,   &g_cnt0, g_list0, CAP0);
    wappend(v && ((sbm[d4.y>>5]>>(d4.y&31))&1u), e0+1, &g_cnt0, g_list0, CAP0);
    wappend(v && ((sbm[d4.z>>5]>>(d4.z&31))&1u), e0+2, &g_cnt0, g_list0, CAP0);
    wappend(v && ((sbm[d4.w>>5]>>(d4.w&31))&1u), e0+3, &g_cnt0, g_list0, CAP0);
  }
}

// full-E scan: collect edges whose dst is in bmG (smem copy). which=1 -> list1, 2 -> list2
__global__ __launch_bounds__(SCAN_THREADS) void k_scan(const int* __restrict__ dstp, int which){
  extern __shared__ unsigned sbm[];
  for (int i = threadIdx.x; i < NWORDS; i += SCAN_THREADS) sbm[i] = g_bmG[i];
  __syncthreads();
  int* cnt  = (which==1) ? &g_cnt1 : &g_cnt2;
  int* list = (which==1) ? g_list1 : g_list2;
  int cap   = (which==1) ? CAP1 : CAP2;
  const int EV = EE/4;
  int stride = gridDim.x*blockDim.x;
  int gtid = blockIdx.x*blockDim.x + threadIdx.x;
  int iters = (EV + stride - 1)/stride;
  for (int it = 0; it < iters; it++){
    int i = gtid + it*stride;
    bool v = i < EV;
    int4 d4 = make_int4(0,0,0,0);
    if (v) d4 = ((const int4*)dstp)[i];
    int e0 = 4*i;
    wappend(v && ((sbm[d4.x>>5]>>(d4.x&31))&1u), e0,   cnt, list, cap);
    wappend(v && ((sbm[d4.y>>5]>>(d4.y&31))&1u), e0+1, cnt, list, cap);
    wappend(v && ((sbm[d4.z>>5]>>(d4.z&31))&1u), e0+2, cnt, list, cap);
    wappend(v && ((sbm[d4.w>>5]>>(d4.w&31))&1u), e0+3, cnt, list, cap);
  }
}

// mark srcs of a list into bmG (frontier growth). which=0 uses list0, 1 uses list1.
__global__ void k_srcs(const int* __restrict__ srcp, int which){
  const int* list = (which==0) ? g_list0 : g_list1;
  int cap         = (which==0) ? CAP0    : CAP1;
  int n = min((which==0) ? g_cnt0 : g_cnt1, cap);
  int stride = gridDim.x*blockDim.x;
  for (int i = blockIdx.x*blockDim.x + threadIdx.x; i < n; i += stride)
    bmset(g_bmG, srcp[list[i]]);
}

// snapshot bmG into node list (1 -> nl1, 2 -> nl2)
__global__ void k_compact(int which){
  int i = blockIdx.x*blockDim.x + threadIdx.x;
  bool p = bmtest(g_bmG, i);
  if (which == 1) wappend(p, i, &g_cntn1, g_nl1, NN);
  else            wappend(p, i, &g_cntn2, g_nl2, NN);
}

// dense h1 with prescale: hs = rsqrt(deg) * (x @ W1).  8 threads/node.
__global__ __launch_bounds__(256) void k_h1(const float* __restrict__ x,
                                            const float* __restrict__ W1){
  __shared__ float sW[128*9];
  int t = threadIdx.x;
  for (int i = t; i < 1024; i += 256) sW[(i>>3)*9 + (i&7)] = W1[i];
  __syncthreads();
  int sub  = t & 7;
  int node = blockIdx.x*32 + (t>>3);
  const float* xr = x + (size_t)node*128 + sub*4;
  float acc[8];
  #pragma unroll
  for (int j=0;j<8;j++) acc[j] = 0.f;
  #pragma unroll
  for (int q=0;q<4;q++){
    float4 v = *(const float4*)(xr + 32*q);
    float xt[4] = {v.x, v.y, v.z, v.w};
    #pragma unroll
    for (int u=0;u<4;u++){
      const float* w = &sW[(32*q + 4*sub + u)*9];
      #pragma unroll
      for (int j=0;j<8;j++) acc[j] += xt[u]*w[j];
    }
  }
  #pragma unroll
  for (int off=4; off; off>>=1){
    #pragma unroll
    for (int j=0;j<8;j++) acc[j] += __shfl_xor_sync(0xffffffffu, acc[j], off);
  }
  if (sub == 0){
    float r = rsqrtf(g_deg[node]);
    float* hp = g_hs + (size_t)node*8;
    *(float4*)hp     = make_float4(acc[0]*r,acc[1]*r,acc[2]*r,acc[3]*r);
    *(float4*)(hp+4) = make_float4(acc[4]*r,acc[5]*r,acc[6]*r,acc[7]*r);
  }
}

// sparse layer-1 aggregation over edges into S2
__global__ __launch_bounds__(256) void k_agg1s(const int* __restrict__ srcp, const int* __restrict__ dstp){
  int n = min(g_cnt2, CAP2);
  int stride = gridDim.x*blockDim.x;
  for (int i = blockIdx.x*blockDim.x + threadIdx.x; i < n; i += stride){
    int e = g_list2[i];
    int s = srcp[e], d = dstp[e];
    const float* hp = g_hs + (size_t)s*8;
    float4 a = *(const float4*)hp, b = *(const float4*)(hp+4);
    float* ap = g_acc1 + (size_t)d*8;
    atomicAdd((float4*)ap, a);
    atomicAdd((float4*)(ap+4), b);
  }
}

// x1 = relu(dis*(acc1+hs)+b1); h2s = dis*(x1@W2). nodes in nl2 (S2).
__global__ __launch_bounds__(256) void k_h2(const float* __restrict__ W2, const float* __restrict__ b1){
  __shared__ float sW[64], sb[8];
  int t = threadIdx.x;
  if (t < 64) sW[t] = W2[t];
  if (t < 8)  sb[t] = b1[t];
  __syncthreads();
  int n = g_cntn2;
  int stride = gridDim.x*blockDim.x;
  for (int i = blockIdx.x*blockDim.x + t; i < n; i += stride){
    int node = g_nl2[i];
    float r = rsqrtf(g_deg[node]);
    const float* ap = g_acc1 + (size_t)node*8;
    const float* hp = g_hs  + (size_t)node*8;
    float x1[8];
    #pragma unroll
    for (int j=0;j<8;j++) x1[j] = fmaxf(r*(ap[j]+hp[j]) + sb[j], 0.f);
    float* h2p = g_h2s + (size_t)node*8;
    #pragma unroll
    for (int j=0;j<8;j++){
      float s2 = 0.f;
      #pragma unroll
      for (int u=0;u<8;u++) s2 += x1[u]*sW[u*8+j];
      h2p[j] = r*s2;
    }
  }
}

__global__ void k_agg2s(const int* __restrict__ srcp, const int* __restrict__ dstp){
  int n = min(g_cnt1, CAP1);
  int stride = gridDim.x*blockDim.x;
  for (int i = blockIdx.x*blockDim.x + threadIdx.x; i < n; i += stride){
    int e = g_list1[i];
    int s = srcp[e], d = dstp[e];
    const float* hp = g_h2s + (size_t)s*8;
    float4 a = *(const float4*)hp, b = *(const float4*)(hp+4);
    float* ap = g_acc2 + (size_t)d*8;
    atomicAdd((float4*)ap, a);
    atomicAdd((float4*)(ap+4), b);
  }
}

// x2 = relu(dis*(acc2+h2s)+b2); h3s = dis*(x2.W3). nodes in nl1 (S1).
__global__ void k_h3(const float* __restrict__ W3, const float* __restrict__ b2){
  int n = g_cntn1;
  int stride = gridDim.x*blockDim.x;
  for (int i = blockIdx.x*blockDim.x + threadIdx.x; i < n; i += stride){
    int node = g_nl1[i];
    float r = rsqrtf(g_deg[node]);
    const float* ap = g_acc2 + (size_t)node*8;
    const float* hp = g_h2s + (size_t)node*8;
    float s2 = 0.f;
    #pragma unroll
    for (int j=0;j<8;j++) s2 += fmaxf(r*(ap[j]+hp[j]) + b2[j], 0.f)*W3[j];
    g_h3s[node] = r*s2;
  }
}

__global__ void k_agg3s(const int* __restrict__ srcp, const int* __restrict__ dstp){
  int n = min(g_cnt0, CAP0);
  int stride = gridDim.x*blockDim.x;
  for (int i = blockIdx.x*blockDim.x + threadIdx.x; i < n; i += stride){
    int e = g_list0[i];
    atomicAdd(&g_acc3[dstp[e]], g_h3s[srcp[e]]);
  }
}

__global__ void k_head(const int* __restrict__ tgt,
                       const float* __restrict__ b1, const float* __restrict__ b2,
                       const float* __restrict__ b3,
                       const float* __restrict__ Wl1, const float* __restrict__ bl1,
                       const float* __restrict__ Wl2, const float* __restrict__ bl2,
                       float* __restrict__ out){
  __shared__ float sW1[17*16], sb1[16], sW2[32], sb2[2];
  int t = threadIdx.x;
  for (int i = t; i < 17*16; i += 64) sW1[i] = Wl1[i];
  if (t < 16) sb1[t] = bl1[t];
  if (t < 32) sW2[t] = Wl2[t];
  if (t < 2)  sb2[t] = bl2[t];
  __syncthreads();
  if (t >= NB) return;
  int node = t*NPG + tgt[t];
  float r = rsqrtf(g_deg[node]);
  float f[17];
  const float* a1 = g_acc1 + (size_t)node*8;
  const float* h1 = g_hs  + (size_t)node*8;
  const float* a2 = g_acc2 + (size_t)node*8;
  const float* h2 = g_h2s + (size_t)node*8;
  #pragma unroll
  for (int j=0;j<8;j++) f[j]   = fmaxf(r*(a1[j]+h1[j]) + b1[j], 0.f);
  #pragma unroll
  for (int j=0;j<8;j++) f[8+j] = fmaxf(r*(a2[j]+h2[j]) + b2[j], 0.f);
  f[16] = fmaxf(r*(g_acc3[node]+g_h3s[node]) + b3[0], 0.f);
  float z[16];
  #pragma unroll
  for (int j=0;j<16;j++){
    float s2 = sb1[j];
    #pragma unroll
    for (int u=0;u<17;u++) s2 += f[u]*sW1[u*16+j];
    z[j] = fmaxf(s2, 0.f);
  }
  #pragma unroll
  for (int o=0;o<2;o++){
    float s2 = sb2[o];
    #pragma unroll
    for (int u=0;u<16;u++) s2 += z[u]*sW2[u*2+o];
    out[t*2+o] = s2;
  }
}

extern "C" void kernel_launch(void* const* d_in, const int* in_sizes, int n_in,
                              void* d_out, int out_size){
  const float* x    = (const float*)d_in[0];
  const int*   ei   = (const int*)  d_in[1];
  const int*   tgt  = (const int*)  d_in[2];
  const float* W1   = (const float*)d_in[3];
  const float* b1   = (const float*)d_in[4];
  const float* W2   = (const float*)d_in[5];
  const float* b2   = (const float*)d_in[6];
  const float* W3   = (const float*)d_in[7];
  const float* b3   = (const float*)d_in[8];
  const float* Wl1  = (const float*)d_in[9];
  const float* bl1  = (const float*)d_in[10];
  const float* Wl2  = (const float*)d_in[11];
  const float* bl2  = (const float*)d_in[12];
  const int* srcp = ei;
  const int* dstp = ei + EE;
  float* out = (float*)d_out;

  static int s_attr_done = 0;
  if (!s_attr_done){
    cudaFuncSetAttribute(k_degscan0, cudaFuncAttributeMaxDynamicSharedMemorySize, NWORDS*4);
    cudaFuncSetAttribute(k_scan,     cudaFuncAttributeMaxDynamicSharedMemorySize, NWORDS*4);
    s_attr_done = 1;
  }

  k_init<<<NN/256, 256>>>();
  k_mark<<<1, 64>>>(tgt);
  k_degscan0<<<SCAN_BLOCKS, SCAN_THREADS, NWORDS*4>>>(dstp);   // deg + list0
  k_srcs<<<64, 256>>>(srcp, 0);                                // bmG = S1
  k_compact<<<NN/256, 256>>>(1);                               // nl1 = S1
  k_scan<<<SCAN_BLOCKS, SCAN_THREADS, NWORDS*4>>>(dstp, 1);    // list1: edges into S1
  k_srcs<<<64, 256>>>(srcp, 1);                                // bmG = S2
  k_compact<<<NN/256, 256>>>(2);                               // nl2 = S2
  k_scan<<<SCAN_BLOCKS, SCAN_THREADS, NWORDS*4>>>(dstp, 2);    // list2: edges into S2
  k_h1<<<NN/32, 256>>>(x, W1);                                 // dense hs = dis*(x@W1)
  k_agg1s<<<512, 256>>>(srcp, dstp);
  k_h2<<<128, 256>>>(W2, b1);
  k_agg2s<<<64, 256>>>(srcp, dstp);
  k_h3<<<64, 256>>>(W3, b2);
  k_agg3s<<<16, 256>>>(srcp, dstp);
  k_head<<<1, 64>>>(tgt, b1, b2, b3, Wl1, bl1, Wl2, bl2, out);
}